// round 13
// baseline (speedup 1.0000x reference)
#include <cuda_runtime.h>

#define N_CELL  50000
#define N_NET   10000
#define N_GCELL 20000
#define NE      100000
#define D       32
#define DPF     16
#define GP      17           // DPF + 1 (bias row)
#define TSRC    16           // source nodes per fused-nnconv block
#define NB_NET_NN (N_NET / TSRC)     // 625
#define NB_GC_NN  (N_GCELL / TSRC)   // 1250
#define CAPN    512          // bin capacity, net side (mean 160)
#define CAPH    256          // bin capacity, gcell side (mean 80)

// ---------------- scratch (static device globals; no allocs) ------------
__device__ __align__(16) float g_agg_net[N_NET * D];
__device__ __align__(16) float g_agg_gc_c[N_GCELL * D];
__device__ __align__(16) float g_agg_gc_pt[N_GCELL * D];
__device__ __align__(16) int g_cnt_pins_src[N_CELL];
__device__ __align__(16) int g_cnt_pins_dst[N_NET];
__device__ __align__(16) int g_cnt_pinned_dst[N_CELL];
__device__ __align__(16) int g_cnt_connect_src[N_GCELL];
__device__ __align__(16) int g_cnt_connect_dst[N_GCELL];
__device__ __align__(16) int g_cnt_pt_src[N_CELL];
__device__ __align__(16) int g_cnt_pt_dst[N_GCELL];
__device__ __align__(16) int g_cnt_pf_dst[N_CELL];
__device__ __align__(16) int g_bincnt_net[NB_NET_NN];
__device__ __align__(16) int g_bincnt_han[NB_GC_NN];
__device__ int g_bin_net[NB_NET_NN * CAPN];
__device__ int g_bin_han[NB_GC_NN * CAPH];

// vector reduction to global (sm_90+)
__device__ __forceinline__ void red_add_f4(float* p, float4 v) {
    asm volatile("red.global.add.v4.f32 [%0], {%1,%2,%3,%4};"
                 :: "l"(p), "f"(v.x), "f"(v.y), "f"(v.z), "f"(v.w) : "memory");
}

__device__ __forceinline__ unsigned cvt_tf32(float x) {
    unsigned r;
    asm("cvt.rna.tf32.f32 %0, %1;" : "=r"(r) : "f"(x));
    return r;
}

__device__ __forceinline__ void mma_tf32(float c[4],
        unsigned a0, unsigned a1, unsigned a2, unsigned a3,
        unsigned b0, unsigned b1) {
    asm("mma.sync.aligned.m16n8k8.row.col.f32.tf32.tf32.f32 "
        "{%0,%1,%2,%3}, {%4,%5,%6,%7}, {%8,%9}, {%0,%1,%2,%3};"
        : "+f"(c[0]), "+f"(c[1]), "+f"(c[2]), "+f"(c[3])
        : "r"(a0), "r"(a1), "r"(a2), "r"(a3), "r"(b0), "r"(b1));
}

// ---------------- kernels ----------------

// zero counts/bins/aggs; pre-init out_cell with summed biases (k_nn REDs into it)
__global__ void k_zero(const float* __restrict__ b_pinned, const float* __restrict__ b_pf,
                       float* __restrict__ out_cell) {
    __shared__ float4 sb4[8];
    if (threadIdx.x < D) {
        float v = b_pinned[threadIdx.x] + b_pf[threadIdx.x];
        ((float*)sb4)[threadIdx.x] = v;
    }
    __syncthreads();
    int tid = blockIdx.x * blockDim.x + threadIdx.x;
    int stride = gridDim.x * blockDim.x;
    float4 z4 = {0.f, 0.f, 0.f, 0.f};
    int4 zi = {0, 0, 0, 0};
    for (int i = tid; i < N_CELL * D / 4; i += stride) {
        ((float4*)out_cell)[i] = sb4[i & 7];
    }
    for (int i = tid; i < N_NET * D / 4; i += stride) ((float4*)g_agg_net)[i] = z4;
    for (int i = tid; i < N_GCELL * D / 4; i += stride) { ((float4*)g_agg_gc_c)[i] = z4; ((float4*)g_agg_gc_pt)[i] = z4; }
    for (int i = tid; i < N_CELL / 4; i += stride) {
        ((int4*)g_cnt_pins_src)[i] = zi; ((int4*)g_cnt_pinned_dst)[i] = zi;
        ((int4*)g_cnt_pt_src)[i] = zi;   ((int4*)g_cnt_pf_dst)[i] = zi;
    }
    for (int i = tid; i < N_NET / 4; i += stride) ((int4*)g_cnt_pins_dst)[i] = zi;
    for (int i = tid; i < N_GCELL / 4; i += stride) {
        ((int4*)g_cnt_connect_src)[i] = zi; ((int4*)g_cnt_connect_dst)[i] = zi;
        ((int4*)g_cnt_pt_dst)[i] = zi;
    }
    for (int i = tid; i < NB_NET_NN; i += stride) g_bincnt_net[i] = 0;
    for (int i = tid; i < NB_GC_NN; i += stride) g_bincnt_han[i] = 0;
}

#define RBLK ((NE + 255) / 256)      // 391 blocks per role

// nn-branch prefix only: dst counts (for mean scaling) + src bins
__global__ void k_prep_nn(const int* __restrict__ pinned_src, const int* __restrict__ pinned_dst,
                          const int* __restrict__ pf_src, const int* __restrict__ pf_dst) {
    int role = blockIdx.x / RBLK;
    int e = (blockIdx.x - role * RBLK) * 256 + threadIdx.x;
    if (e >= NE) return;
    switch (role) {
        case 0: atomicAdd(&g_cnt_pinned_dst[pinned_dst[e]], 1); break;
        case 1: atomicAdd(&g_cnt_pf_dst[pf_dst[e]], 1); break;
        case 2: {
            int b = pinned_src[e] >> 4;
            int s = atomicAdd(&g_bincnt_net[b], 1);
            if (s < CAPN) g_bin_net[b * CAPN + s] = e;
            break;
        }
        default: {
            int b = pf_src[e] >> 4;
            int s = atomicAdd(&g_bincnt_han[b], 1);
            if (s < CAPH) g_bin_han[b * CAPH + s] = e;
            break;
        }
    }
}

// gc-branch prefix only: src counts (for norm) + dst counts (for epilogue)
__global__ void k_prep_gc(const int* __restrict__ pins_src, const int* __restrict__ pins_dst,
                          const int* __restrict__ connect_src, const int* __restrict__ connect_dst,
                          const int* __restrict__ pt_src, const int* __restrict__ pt_dst) {
    int role = blockIdx.x / RBLK;
    int e = (blockIdx.x - role * RBLK) * 256 + threadIdx.x;
    if (e >= NE) return;
    switch (role) {
        case 0: atomicAdd(&g_cnt_pins_src[pins_src[e]], 1); break;
        case 1: atomicAdd(&g_cnt_connect_src[connect_src[e]], 1); break;
        case 2: atomicAdd(&g_cnt_pt_src[pt_src[e]], 1); break;
        case 3: atomicAdd(&g_cnt_pins_dst[pins_dst[e]], 1); break;
        case 4: atomicAdd(&g_cnt_connect_dst[connect_dst[e]], 1); break;
        default: atomicAdd(&g_cnt_pt_dst[pt_dst[e]], 1); break;
    }
}

// GraphConv scatter: 8 threads/edge, float4 vector REDs. 3 edge sets.
__global__ void k_gc_scatter(const float* __restrict__ node_feat, const float* __restrict__ hanna_feat,
                             const int* __restrict__ pins_src, const int* __restrict__ pins_dst,
                             const int* __restrict__ connect_src, const int* __restrict__ connect_dst,
                             const int* __restrict__ pt_src, const int* __restrict__ pt_dst) {
    int gt = blockIdx.x * blockDim.x + threadIdx.x;
    int ge = gt >> 3;
    int j = gt & 7;
    if (ge >= 3 * NE) return;
    const float* feat; const int* srcA; const int* dstA; const int* cnt; float* agg; int e;
    if (ge < NE)          { e = ge;          feat = node_feat;  srcA = pins_src;    dstA = pins_dst;    cnt = g_cnt_pins_src;    agg = g_agg_net;   }
    else if (ge < 2 * NE) { e = ge - NE;     feat = hanna_feat; srcA = connect_src; dstA = connect_dst; cnt = g_cnt_connect_src; agg = g_agg_gc_c;  }
    else                  { e = ge - 2 * NE; feat = node_feat;  srcA = pt_src;      dstA = pt_dst;      cnt = g_cnt_pt_src;      agg = g_agg_gc_pt; }
    int s = srcA[e], d = dstA[e];
    float scale = rsqrtf((float)max(cnt[s], 1));
    float4 f = ((const float4*)(feat + (size_t)s * D))[j];
    f.x *= scale; f.y *= scale; f.z *= scale; f.w *= scale;
    red_add_f4(agg + (size_t)d * D + j * 4, f);
}

// Fused NNConv: block owns TSRC=16 consecutive source nodes (== one bin).
// Phase 1 (tf32 tensor cores): G(16x544) = h(16x32) @ Wr(32x544) via mma.m16n8k8.
// Phase 2: per-edge message scaled by 1/deg(dst), RED into bias-pre-init out_cell.
__global__ __launch_bounds__(544, 2) void k_nn(
        const float* __restrict__ net_feat, const float* __restrict__ hanna_feat,
        const float* __restrict__ W_topo, const float* __restrict__ b_topo,
        const float* __restrict__ pin_feat, const float* __restrict__ edge_feat,
        const int* __restrict__ pinned_src, const int* __restrict__ pinned_dst,
        const int* __restrict__ pf_src, const int* __restrict__ pf_dst,
        float* __restrict__ out_cell) {
    __shared__ float sh_h[TSRC * D];              // 16 x 32
    __shared__ float sh_G[TSRC * GP * D];         // 16 x 17 x 32 = 34.8 KB

    int bid = blockIdx.x;
    const float* h; const float* ef; const int* srcA; const int* dstA;
    const int* bins; const int* bincnt; const int* cntD; int first, cap, bin;
    if (bid < NB_NET_NN) {
        bin = bid; first = bid * TSRC;
        h = net_feat; ef = pin_feat; srcA = pinned_src; dstA = pinned_dst;
        bins = g_bin_net; bincnt = g_bincnt_net; cntD = g_cnt_pinned_dst; cap = CAPN;
    } else {
        bin = bid - NB_NET_NN; first = bin * TSRC;
        h = hanna_feat; ef = edge_feat; srcA = pf_src; dstA = pf_dst;
        bins = g_bin_han; bincnt = g_bincnt_han; cntD = g_cnt_pf_dst; cap = CAPH;
    }
    int tid = threadIdx.x;

    if (tid < TSRC * D) sh_h[tid] = h[(size_t)first * D + tid];
    __syncthreads();

    // ---- phase 1: tf32 tensor-core GEMM (warp p computes G[:, p, :]) ----
    {
        int p = tid >> 5;
        int lane = tid & 31;
        int grp = lane >> 2, tig = lane & 3;
        const float* Bp = (p < DPF) ? (W_topo + p * (D * D)) : b_topo;

        unsigned a[4][4];
#pragma unroll
        for (int ks = 0; ks < 4; ks++) {
            a[ks][0] = cvt_tf32(sh_h[grp * D + 8 * ks + tig]);
            a[ks][1] = cvt_tf32(sh_h[(grp + 8) * D + 8 * ks + tig]);
            a[ks][2] = cvt_tf32(sh_h[grp * D + 8 * ks + tig + 4]);
            a[ks][3] = cvt_tf32(sh_h[(grp + 8) * D + 8 * ks + tig + 4]);
        }
#pragma unroll
        for (int nt = 0; nt < 4; nt++) {
            float c[4] = {0.f, 0.f, 0.f, 0.f};
#pragma unroll
            for (int ks = 0; ks < 4; ks++) {
                unsigned b0 = cvt_tf32(Bp[(8 * ks + tig) * D + 8 * nt + grp]);
                unsigned b1 = cvt_tf32(Bp[(8 * ks + tig + 4) * D + 8 * nt + grp]);
                mma_tf32(c, a[ks][0], a[ks][1], a[ks][2], a[ks][3], b0, b1);
            }
            *(float2*)&sh_G[grp * (GP * D) + p * D + 8 * nt + 2 * tig] = make_float2(c[0], c[1]);
            *(float2*)&sh_G[(grp + 8) * (GP * D) + p * D + 8 * nt + 2 * tig] = make_float2(c[2], c[3]);
        }
    }
    __syncthreads();

    // ---- phase 2: edge streaming from this block's bin ----
    int bs = bin * cap;
    int nE = min(bincnt[bin], cap);
    int grp8 = tid >> 3;       // 68 groups of 8
    int j8 = tid & 7;
    int iters = (nE + 67) / 68;
    for (int it = 0; it < iters; it++) {
        int j = it * 68 + grp8;
        bool valid = j < nE;
        int eid = bins[bs + (valid ? j : 0)];
        int s = srcA[eid];
        int t = s - first;
        int d = dstA[eid];
        float inv = 1.0f / (float)max(cntD[d], 1);
        float2 c2 = ((const float2*)(ef + (size_t)eid * DPF))[j8];
        const float* Gt = sh_G + t * (GP * D);
        float4 a = {0.f, 0.f, 0.f, 0.f};
#pragma unroll
        for (int p = 0; p < GP; p++) {
            float cp;
            if (p < DPF) cp = __shfl_sync(0xffffffffu, (p & 1) ? c2.y : c2.x, p >> 1, 8);
            else cp = 1.f;
            float4 g4 = ((const float4*)(Gt + p * D))[j8];
            a.x = fmaf(cp, g4.x, a.x);
            a.y = fmaf(cp, g4.y, a.y);
            a.z = fmaf(cp, g4.z, a.z);
            a.w = fmaf(cp, g4.w, a.w);
        }
        a.x *= inv; a.y *= inv; a.z *= inv; a.w *= inv;
        if (valid) red_add_f4(out_cell + (size_t)d * D + j8 * 4, a);
    }
}

// net + gcell epilogue (cell outputs are produced by k_nn directly)
#define NBF_NET  (N_NET / 8)            // 1250
#define NBF_GC   (N_GCELL / 8)          // 2500
__global__ void k_final_netgc(const float* __restrict__ net_feat,
                              const float* __restrict__ W_pins, const float* __restrict__ b_pins,
                              const float* __restrict__ W_net, const float* __restrict__ b_net,
                              const float* __restrict__ W_connect, const float* __restrict__ b_connect,
                              const float* __restrict__ W_pt, const float* __restrict__ b_pt,
                              float* __restrict__ out_net, float* __restrict__ out_gcell) {
    __shared__ float sW1[D * D], sW2[D * D];
    int b = blockIdx.x;
    if (b < NBF_NET) {
        for (int i = threadIdx.x; i < D * D; i += 256) { sW1[i] = W_pins[i]; sW2[i] = W_net[i]; }
        __syncthreads();
        int n = b * 8 + (threadIdx.x >> 5);
        int o = threadIdx.x & 31;
        float acc = 0.f, acc2 = 0.f;
#pragma unroll
        for (int i = 0; i < D; i++) {
            acc  = fmaf(g_agg_net[n * D + i], sW1[i * D + o], acc);
            acc2 = fmaf(net_feat[n * D + i],  sW2[i * D + o], acc2);
        }
        float ddn = rsqrtf((float)max(g_cnt_pins_dst[n], 1));
        out_net[n * D + o] = acc * ddn + b_pins[o] + acc2 + b_net[o];
        return;
    }
    {
        for (int i = threadIdx.x; i < D * D; i += 256) { sW1[i] = W_connect[i]; sW2[i] = W_pt[i]; }
        __syncthreads();
        int g = (b - NBF_NET) * 8 + (threadIdx.x >> 5);
        int o = threadIdx.x & 31;
        float acc = 0.f, acc2 = 0.f;
#pragma unroll
        for (int i = 0; i < D; i++) {
            acc  = fmaf(g_agg_gc_c[g * D + i],  sW1[i * D + o], acc);
            acc2 = fmaf(g_agg_gc_pt[g * D + i], sW2[i * D + o], acc2);
        }
        float dc = rsqrtf((float)max(g_cnt_connect_dst[g], 1));
        float dp = rsqrtf((float)max(g_cnt_pt_dst[g], 1));
        out_gcell[g * D + o] = acc * dc + b_connect[o] + acc2 * dp + b_pt[o];
    }
}

// ---------------- launch ----------------

extern "C" void kernel_launch(void* const* d_in, const int* in_sizes, int n_in,
                              void* d_out, int out_size) {
    const float* node_feat   = (const float*)d_in[0];
    const float* net_feat    = (const float*)d_in[1];
    const float* pin_feat    = (const float*)d_in[2];
    const float* hanna_feat  = (const float*)d_in[3];
    const float* edge_feat   = (const float*)d_in[4];
    const int* pins_src      = (const int*)d_in[5];
    const int* pins_dst      = (const int*)d_in[6];
    const int* pinned_src    = (const int*)d_in[7];
    const int* pinned_dst    = (const int*)d_in[8];
    const int* connect_src   = (const int*)d_in[9];
    const int* connect_dst   = (const int*)d_in[10];
    const int* pt_src        = (const int*)d_in[11];
    const int* pt_dst        = (const int*)d_in[12];
    const int* pf_src        = (const int*)d_in[13];
    const int* pf_dst        = (const int*)d_in[14];
    const float* W_net       = (const float*)d_in[15];
    const float* b_net       = (const float*)d_in[16];
    const float* W_topo      = (const float*)d_in[17];
    const float* b_topo      = (const float*)d_in[18];
    const float* W_pins      = (const float*)d_in[19];
    const float* b_pins      = (const float*)d_in[20];
    const float* W_connect   = (const float*)d_in[21];
    const float* b_connect   = (const float*)d_in[22];
    const float* W_pt        = (const float*)d_in[23];
    const float* b_pt        = (const float*)d_in[24];
    const float* b_pinned    = (const float*)d_in[25];
    const float* b_pf        = (const float*)d_in[26];

    float* out       = (float*)d_out;
    float* out_cell  = out;
    float* out_net   = out + (size_t)N_CELL * D;
    float* out_gcell = out + (size_t)(N_CELL + N_NET) * D;

    static cudaStream_t s1 = nullptr;
    static cudaEvent_t evZ = nullptr, evNN = nullptr;
    if (s1 == nullptr) {
        int lo, hi;
        cudaDeviceGetStreamPriorityRange(&lo, &hi);
        cudaStreamCreateWithPriority(&s1, cudaStreamNonBlocking, hi);  // highest priority for nn branch
        cudaEventCreateWithFlags(&evZ, cudaEventDisableTiming);
        cudaEventCreateWithFlags(&evNN, cudaEventDisableTiming);
    }

    // main: zero (also bias-inits out_cell)
    k_zero<<<1024, 256>>>(b_pinned, b_pf, out_cell);
    cudaEventRecord(evZ, 0);

    // s1 branch (high priority): prep_nn -> nn (writes out_cell directly)
    cudaStreamWaitEvent(s1, evZ, 0);
    k_prep_nn<<<4 * RBLK, 256, 0, s1>>>(pinned_src, pinned_dst, pf_src, pf_dst);
    k_nn<<<NB_NET_NN + NB_GC_NN, 544, 0, s1>>>(net_feat, hanna_feat, W_topo, b_topo,
                                               pin_feat, edge_feat,
                                               pinned_src, pinned_dst, pf_src, pf_dst,
                                               out_cell);
    cudaEventRecord(evNN, s1);

    // main branch: prep_gc -> gc_scatter -> final_netgc (writes out_net/out_gcell)
    k_prep_gc<<<6 * RBLK, 256>>>(pins_src, pins_dst, connect_src, connect_dst,
                                 pt_src, pt_dst);
    k_gc_scatter<<<(3 * NE * 8 + 255) / 256, 256>>>(node_feat, hanna_feat,
                                                    pins_src, pins_dst,
                                                    connect_src, connect_dst,
                                                    pt_src, pt_dst);
    k_final_netgc<<<NBF_NET + NBF_GC, 256>>>(net_feat, W_pins, b_pins, W_net, b_net,
                                             W_connect, b_connect, W_pt, b_pt,
                                             out_net, out_gcell);

    // join
    cudaStreamWaitEvent(0, evNN, 0);
}

// round 16
// speedup vs baseline: 1.0372x; 1.0372x over previous
#include <cuda_runtime.h>

#define N_CELL  50000
#define N_NET   10000
#define N_GCELL 20000
#define NE      100000
#define D       32
#define DPF     16
#define GP      17           // DPF + 1 (bias row)
#define TSRC    16           // source nodes per fused-nnconv block
#define NB_NET_NN (N_NET / TSRC)     // 625
#define NB_GC_NN  (N_GCELL / TSRC)   // 1250
#define CAPN    512          // bin capacity, net side (mean 160)
#define CAPH    256          // bin capacity, gcell side (mean 80)

// ---------------- scratch (static device globals; no allocs) ------------
__device__ __align__(16) float g_agg_net[N_NET * D];
__device__ __align__(16) float g_agg_gc_c[N_GCELL * D];
__device__ __align__(16) float g_agg_gc_pt[N_GCELL * D];
__device__ __align__(16) int g_cnt_pins_src[N_CELL];
__device__ __align__(16) int g_cnt_pins_dst[N_NET];
__device__ __align__(16) int g_cnt_pinned_dst[N_CELL];
__device__ __align__(16) int g_cnt_connect_src[N_GCELL];
__device__ __align__(16) int g_cnt_connect_dst[N_GCELL];
__device__ __align__(16) int g_cnt_pt_src[N_CELL];
__device__ __align__(16) int g_cnt_pt_dst[N_GCELL];
__device__ __align__(16) int g_cnt_pf_dst[N_CELL];
__device__ __align__(16) int g_bincnt_net[NB_NET_NN];
__device__ __align__(16) int g_bincnt_han[NB_GC_NN];
__device__ __align__(16) int2 g_bin_net[NB_NET_NN * CAPN];   // (.x = (eid<<4)|t, .y = dst)
__device__ __align__(16) int2 g_bin_han[NB_GC_NN * CAPH];

// vector reduction to global (sm_90+)
__device__ __forceinline__ void red_add_f4(float* p, float4 v) {
    asm volatile("red.global.add.v4.f32 [%0], {%1,%2,%3,%4};"
                 :: "l"(p), "f"(v.x), "f"(v.y), "f"(v.z), "f"(v.w) : "memory");
}

// ---------------- kernels ----------------

// zero counts/bins/aggs; pre-init out_cell with summed biases (k_nn REDs into it)
__global__ void k_zero(const float* __restrict__ b_pinned, const float* __restrict__ b_pf,
                       float* __restrict__ out_cell) {
    __shared__ float4 sb4[8];
    if (threadIdx.x < D) {
        float v = b_pinned[threadIdx.x] + b_pf[threadIdx.x];
        ((float*)sb4)[threadIdx.x] = v;
    }
    __syncthreads();
    int tid = blockIdx.x * blockDim.x + threadIdx.x;
    int stride = gridDim.x * blockDim.x;
    float4 z4 = {0.f, 0.f, 0.f, 0.f};
    int4 zi = {0, 0, 0, 0};
    for (int i = tid; i < N_CELL * D / 4; i += stride) {
        ((float4*)out_cell)[i] = sb4[i & 7];
    }
    for (int i = tid; i < N_NET * D / 4; i += stride) ((float4*)g_agg_net)[i] = z4;
    for (int i = tid; i < N_GCELL * D / 4; i += stride) { ((float4*)g_agg_gc_c)[i] = z4; ((float4*)g_agg_gc_pt)[i] = z4; }
    for (int i = tid; i < N_CELL / 4; i += stride) {
        ((int4*)g_cnt_pins_src)[i] = zi; ((int4*)g_cnt_pinned_dst)[i] = zi;
        ((int4*)g_cnt_pt_src)[i] = zi;   ((int4*)g_cnt_pf_dst)[i] = zi;
    }
    for (int i = tid; i < N_NET / 4; i += stride) ((int4*)g_cnt_pins_dst)[i] = zi;
    for (int i = tid; i < N_GCELL / 4; i += stride) {
        ((int4*)g_cnt_connect_src)[i] = zi; ((int4*)g_cnt_connect_dst)[i] = zi;
        ((int4*)g_cnt_pt_dst)[i] = zi;
    }
    for (int i = tid; i < NB_NET_NN; i += stride) g_bincnt_net[i] = 0;
    for (int i = tid; i < NB_GC_NN; i += stride) g_bincnt_han[i] = 0;
}

#define RBLK ((NE + 255) / 256)      // 391 blocks per role

// nn-branch prefix only: dst counts + packed (eid|t, dst) src bins
__global__ void k_prep_nn(const int* __restrict__ pinned_src, const int* __restrict__ pinned_dst,
                          const int* __restrict__ pf_src, const int* __restrict__ pf_dst) {
    int role = blockIdx.x / RBLK;
    int e = (blockIdx.x - role * RBLK) * 256 + threadIdx.x;
    if (e >= NE) return;
    switch (role) {
        case 0: atomicAdd(&g_cnt_pinned_dst[pinned_dst[e]], 1); break;
        case 1: atomicAdd(&g_cnt_pf_dst[pf_dst[e]], 1); break;
        case 2: {
            int src = pinned_src[e];
            int b = src >> 4;
            int s = atomicAdd(&g_bincnt_net[b], 1);
            if (s < CAPN) g_bin_net[b * CAPN + s] = make_int2((e << 4) | (src & 15), pinned_dst[e]);
            break;
        }
        default: {
            int src = pf_src[e];
            int b = src >> 4;
            int s = atomicAdd(&g_bincnt_han[b], 1);
            if (s < CAPH) g_bin_han[b * CAPH + s] = make_int2((e << 4) | (src & 15), pf_dst[e]);
            break;
        }
    }
}

// gc-branch prefix only: src counts (for norm) + dst counts (for epilogue)
__global__ void k_prep_gc(const int* __restrict__ pins_src, const int* __restrict__ pins_dst,
                          const int* __restrict__ connect_src, const int* __restrict__ connect_dst,
                          const int* __restrict__ pt_src, const int* __restrict__ pt_dst) {
    int role = blockIdx.x / RBLK;
    int e = (blockIdx.x - role * RBLK) * 256 + threadIdx.x;
    if (e >= NE) return;
    switch (role) {
        case 0: atomicAdd(&g_cnt_pins_src[pins_src[e]], 1); break;
        case 1: atomicAdd(&g_cnt_connect_src[connect_src[e]], 1); break;
        case 2: atomicAdd(&g_cnt_pt_src[pt_src[e]], 1); break;
        case 3: atomicAdd(&g_cnt_pins_dst[pins_dst[e]], 1); break;
        case 4: atomicAdd(&g_cnt_connect_dst[connect_dst[e]], 1); break;
        default: atomicAdd(&g_cnt_pt_dst[pt_dst[e]], 1); break;
    }
}

// GraphConv scatter: 8 threads/edge, float4 vector REDs. 3 edge sets.
__global__ void k_gc_scatter(const float* __restrict__ node_feat, const float* __restrict__ hanna_feat,
                             const int* __restrict__ pins_src, const int* __restrict__ pins_dst,
                             const int* __restrict__ connect_src, const int* __restrict__ connect_dst,
                             const int* __restrict__ pt_src, const int* __restrict__ pt_dst) {
    int gt = blockIdx.x * blockDim.x + threadIdx.x;
    int ge = gt >> 3;
    int j = gt & 7;
    if (ge >= 3 * NE) return;
    const float* feat; const int* srcA; const int* dstA; const int* cnt; float* agg; int e;
    if (ge < NE)          { e = ge;          feat = node_feat;  srcA = pins_src;    dstA = pins_dst;    cnt = g_cnt_pins_src;    agg = g_agg_net;   }
    else if (ge < 2 * NE) { e = ge - NE;     feat = hanna_feat; srcA = connect_src; dstA = connect_dst; cnt = g_cnt_connect_src; agg = g_agg_gc_c;  }
    else                  { e = ge - 2 * NE; feat = node_feat;  srcA = pt_src;      dstA = pt_dst;      cnt = g_cnt_pt_src;      agg = g_agg_gc_pt; }
    int s = srcA[e], d = dstA[e];
    float scale = rsqrtf((float)max(cnt[s], 1));
    float4 f = ((const float4*)(feat + (size_t)s * D))[j];
    f.x *= scale; f.y *= scale; f.z *= scale; f.w *= scale;
    red_add_f4(agg + (size_t)d * D + j * 4, f);
}

// Fused NNConv: block owns TSRC=16 consecutive source nodes (== one bin).
// Phase 1 (FFMA, register-tiled): G in shared.
// Phase 2: one int2 bin load gives (eid, t, dst); ef+cntD loads issue in parallel;
//          message scaled by 1/deg(dst), RED into bias-pre-init out_cell.
__global__ __launch_bounds__(544, 2) void k_nn(
        const float* __restrict__ net_feat, const float* __restrict__ hanna_feat,
        const float* __restrict__ W_topo, const float* __restrict__ b_topo,
        const float* __restrict__ pin_feat, const float* __restrict__ edge_feat,
        float* __restrict__ out_cell) {
    __shared__ float4 sh_h4[TSRC * 8];            // 16 rows x 32 feats
    __shared__ float sh_G[TSRC * GP * D];         // 16 x 17 x 32 = 34.8 KB

    int bid = blockIdx.x;
    const float* h; const float* ef; const int2* bins; const int* bincnt;
    const int* cntD; int first, cap, bin;
    if (bid < NB_NET_NN) {
        bin = bid; first = bid * TSRC;
        h = net_feat; ef = pin_feat;
        bins = g_bin_net; bincnt = g_bincnt_net; cntD = g_cnt_pinned_dst; cap = CAPN;
    } else {
        bin = bid - NB_NET_NN; first = bin * TSRC;
        h = hanna_feat; ef = edge_feat;
        bins = g_bin_han; bincnt = g_bincnt_han; cntD = g_cnt_pf_dst; cap = CAPH;
    }
    int tid = threadIdx.x;

    if (tid < TSRC * D) ((float*)sh_h4)[tid] = h[(size_t)first * D + tid];
    __syncthreads();

    // ---- phase 1: G compute (thread = (p, o), 16 accumulators) ----
    {
        int p = tid >> 5, o = tid & 31;
        const float* w = ((p < DPF) ? (W_topo + p * (D * D)) : b_topo) + o;
        float acc[TSRC];
#pragma unroll
        for (int t = 0; t < TSRC; t++) acc[t] = 0.f;
#pragma unroll
        for (int i4 = 0; i4 < 8; i4++) {
            float w0 = w[(i4 * 4 + 0) * D];
            float w1 = w[(i4 * 4 + 1) * D];
            float w2 = w[(i4 * 4 + 2) * D];
            float w3 = w[(i4 * 4 + 3) * D];
#pragma unroll
            for (int t = 0; t < TSRC; t++) {
                float4 h4 = sh_h4[t * 8 + i4];
                acc[t] = fmaf(h4.x, w0, fmaf(h4.y, w1, fmaf(h4.z, w2, fmaf(h4.w, w3, acc[t]))));
            }
        }
#pragma unroll
        for (int t = 0; t < TSRC; t++) sh_G[t * (GP * D) + p * D + o] = acc[t];
    }
    __syncthreads();

    // ---- phase 2: edge streaming from this block's bin ----
    int bs = bin * cap;
    int nE = min(bincnt[bin], cap);
    int grp = tid >> 3;        // 68 groups of 8
    int j8 = tid & 7;
    int iters = (nE + 67) / 68;
    for (int it = 0; it < iters; it++) {
        int j = it * 68 + grp;
        bool valid = j < nE;
        int2 pk = bins[bs + (valid ? j : 0)];
        int eid = pk.x >> 4;
        int t = pk.x & 15;
        int d = pk.y;
        // these two loads are independent — issue together
        float inv = 1.0f / (float)max(cntD[d], 1);
        float2 c2 = ((const float2*)(ef + (size_t)eid * DPF))[j8];
        const float* Gt = sh_G + t * (GP * D);
        float4 a = {0.f, 0.f, 0.f, 0.f};
#pragma unroll
        for (int p = 0; p < GP; p++) {
            float cp;
            if (p < DPF) cp = __shfl_sync(0xffffffffu, (p & 1) ? c2.y : c2.x, p >> 1, 8);
            else cp = 1.f;
            float4 g4 = ((const float4*)(Gt + p * D))[j8];
            a.x = fmaf(cp, g4.x, a.x);
            a.y = fmaf(cp, g4.y, a.y);
            a.z = fmaf(cp, g4.z, a.z);
            a.w = fmaf(cp, g4.w, a.w);
        }
        a.x *= inv; a.y *= inv; a.z *= inv; a.w *= inv;
        if (valid) red_add_f4(out_cell + (size_t)d * D + j8 * 4, a);
    }
}

// net + gcell epilogue (cell outputs are produced by k_nn directly)
#define NBF_NET  (N_NET / 8)            // 1250
#define NBF_GC   (N_GCELL / 8)          // 2500
__global__ void k_final_netgc(const float* __restrict__ net_feat,
                              const float* __restrict__ W_pins, const float* __restrict__ b_pins,
                              const float* __restrict__ W_net, const float* __restrict__ b_net,
                              const float* __restrict__ W_connect, const float* __restrict__ b_connect,
                              const float* __restrict__ W_pt, const float* __restrict__ b_pt,
                              float* __restrict__ out_net, float* __restrict__ out_gcell) {
    __shared__ float sW1[D * D], sW2[D * D];
    int b = blockIdx.x;
    if (b < NBF_NET) {
        for (int i = threadIdx.x; i < D * D; i += 256) { sW1[i] = W_pins[i]; sW2[i] = W_net[i]; }
        __syncthreads();
        int n = b * 8 + (threadIdx.x >> 5);
        int o = threadIdx.x & 31;
        float acc = 0.f, acc2 = 0.f;
#pragma unroll
        for (int i = 0; i < D; i++) {
            acc  = fmaf(g_agg_net[n * D + i], sW1[i * D + o], acc);
            acc2 = fmaf(net_feat[n * D + i],  sW2[i * D + o], acc2);
        }
        float ddn = rsqrtf((float)max(g_cnt_pins_dst[n], 1));
        out_net[n * D + o] = acc * ddn + b_pins[o] + acc2 + b_net[o];
        return;
    }
    {
        for (int i = threadIdx.x; i < D * D; i += 256) { sW1[i] = W_connect[i]; sW2[i] = W_pt[i]; }
        __syncthreads();
        int g = (b - NBF_NET) * 8 + (threadIdx.x >> 5);
        int o = threadIdx.x & 31;
        float acc = 0.f, acc2 = 0.f;
#pragma unroll
        for (int i = 0; i < D; i++) {
            acc  = fmaf(g_agg_gc_c[g * D + i],  sW1[i * D + o], acc);
            acc2 = fmaf(g_agg_gc_pt[g * D + i], sW2[i * D + o], acc2);
        }
        float dc = rsqrtf((float)max(g_cnt_connect_dst[g], 1));
        float dp = rsqrtf((float)max(g_cnt_pt_dst[g], 1));
        out_gcell[g * D + o] = acc * dc + b_connect[o] + acc2 * dp + b_pt[o];
    }
}

// ---------------- launch ----------------

extern "C" void kernel_launch(void* const* d_in, const int* in_sizes, int n_in,
                              void* d_out, int out_size) {
    const float* node_feat   = (const float*)d_in[0];
    const float* net_feat    = (const float*)d_in[1];
    const float* pin_feat    = (const float*)d_in[2];
    const float* hanna_feat  = (const float*)d_in[3];
    const float* edge_feat   = (const float*)d_in[4];
    const int* pins_src      = (const int*)d_in[5];
    const int* pins_dst      = (const int*)d_in[6];
    const int* pinned_src    = (const int*)d_in[7];
    const int* pinned_dst    = (const int*)d_in[8];
    const int* connect_src   = (const int*)d_in[9];
    const int* connect_dst   = (const int*)d_in[10];
    const int* pt_src        = (const int*)d_in[11];
    const int* pt_dst        = (const int*)d_in[12];
    const int* pf_src        = (const int*)d_in[13];
    const int* pf_dst        = (const int*)d_in[14];
    const float* W_net       = (const float*)d_in[15];
    const float* b_net       = (const float*)d_in[16];
    const float* W_topo      = (const float*)d_in[17];
    const float* b_topo      = (const float*)d_in[18];
    const float* W_pins      = (const float*)d_in[19];
    const float* b_pins      = (const float*)d_in[20];
    const float* W_connect   = (const float*)d_in[21];
    const float* b_connect   = (const float*)d_in[22];
    const float* W_pt        = (const float*)d_in[23];
    const float* b_pt        = (const float*)d_in[24];
    const float* b_pinned    = (const float*)d_in[25];
    const float* b_pf        = (const float*)d_in[26];

    float* out       = (float*)d_out;
    float* out_cell  = out;
    float* out_net   = out + (size_t)N_CELL * D;
    float* out_gcell = out + (size_t)(N_CELL + N_NET) * D;

    static cudaStream_t s1 = nullptr;
    static cudaEvent_t evZ = nullptr, evNN = nullptr;
    if (s1 == nullptr) {
        int lo, hi;
        cudaDeviceGetStreamPriorityRange(&lo, &hi);
        cudaStreamCreateWithPriority(&s1, cudaStreamNonBlocking, hi);
        cudaEventCreateWithFlags(&evZ, cudaEventDisableTiming);
        cudaEventCreateWithFlags(&evNN, cudaEventDisableTiming);
    }

    // submission order chosen so k_nn is launch index 3 (ncu profiles idx 3):
    // 0: zero, 1: prep_nn(s1), 2: prep_gc(main), 3: nn(s1), 4: gc_scatter(main), 5: final(main)

    k_zero<<<1024, 256>>>(b_pinned, b_pf, out_cell);                       // 0
    cudaEventRecord(evZ, 0);

    cudaStreamWaitEvent(s1, evZ, 0);
    k_prep_nn<<<4 * RBLK, 256, 0, s1>>>(pinned_src, pinned_dst, pf_src, pf_dst);   // 1

    k_prep_gc<<<6 * RBLK, 256>>>(pins_src, pins_dst, connect_src, connect_dst,
                                 pt_src, pt_dst);                          // 2

    k_nn<<<NB_NET_NN + NB_GC_NN, 544, 0, s1>>>(net_feat, hanna_feat, W_topo, b_topo,
                                               pin_feat, edge_feat, out_cell);     // 3
    cudaEventRecord(evNN, s1);

    k_gc_scatter<<<(3 * NE * 8 + 255) / 256, 256>>>(node_feat, hanna_feat,
                                                    pins_src, pins_dst,
                                                    connect_src, connect_dst,
                                                    pt_src, pt_dst);       // 4
    k_final_netgc<<<NBF_NET + NBF_GC, 256>>>(net_feat, W_pins, b_pins, W_net, b_net,
                                             W_connect, b_connect, W_pt, b_pt,
                                             out_net, out_gcell);          // 5

    cudaStreamWaitEvent(0, evNN, 0);
}